// round 14
// baseline (speedup 1.0000x reference)
#include <cuda_runtime.h>
#include <cstdint>

// Problem constants
#define Bn  16
#define Cn  32
#define Nn  128
#define Tn  12
#define COn 64
#define NT  (Nn * Tn)          // 1536 floats per (b,i,j) row of A
#define NT4 (NT / 4)           // 384 float4
#define NSLICE (Bn * Cn)       // 512 (b,i) slices

// 128 persistent CTAs (1/SM via smem pad). 896 threads:
//   threads [0,768): prop (EXACT R3 loop, named barrier 1)
//   threads [768,896): mix workers (named barrier 2), hidden under prop
#define PROP_CTAS   128
#define NPROP       768
#define NMIX        128
#define THREADS     (NPROP + NMIX)
#define NGRP 4
#define GSZ  192
#define JPG  (Nn / NGRP)       // 32
#define NITER (NSLICE / PROP_CTAS)   // 4
#define PROP_PAD (150 * 1024)  // dynamic smem: 1-CTA/SM limiter; mix buffers live here

// mix tiling: 64 outs x 64 cols; 24 tiles/batch; 96 tiles per iteration group
#define MIX_NCB 24
#define MIX_TILES_PER_GROUP 96

// Scratch: h = concat([x1, x2], channel axis) -> [B][2C][N*T] = 6.3 MB
__device__ float g_h[(size_t)Bn * 2 * Cn * NT];
// per-iteration completion counters; memset to 0 each replay (captured node)
__device__ unsigned int g_done[NITER];

extern __shared__ char s_pad[];   // [0,16K): mix hs; [16K,32K): mix Ws; [32K,+256): bias

__device__ __forceinline__ void fma4(float4& acc, const float4 a, const float4 v) {
    acc.x = fmaf(a.x, v.x, acc.x);
    acc.y = fmaf(a.y, v.y, acc.y);
    acc.z = fmaf(a.z, v.z, acc.z);
    acc.w = fmaf(a.w, v.w, acc.w);
}
__device__ __forceinline__ float4 add4(const float4 a, const float4 b) {
    return make_float4(a.x + b.x, a.y + b.y, a.z + b.z, a.w + b.w);
}
__device__ __forceinline__ unsigned int ld_vol_u32(const unsigned int* p) {
    unsigned int v;
    asm volatile("ld.volatile.global.u32 %0, [%1];" : "=r"(v) : "l"(p));
    return v;
}
#define BAR_PROP() asm volatile("bar.sync 1, %0;" :: "r"(NPROP) : "memory")
#define BAR_MIX()  asm volatile("bar.sync 2, %0;" :: "r"(NMIX)  : "memory")

// ---------------------------------------------------------------------------
// Single kernel, warp-specialized:
// PROP (768 thr): exact R3 fused order-1/order-2 propagation. Pass 1 streams
//   each slice from HBM (fills L2); pass 2 re-reads from L2. Phase-locked
//   footprint 128 x 786KB = 100MB <= 126MB. After iteration it, signals
//   g_done[it] (batches 4it..4it+3 complete).
// MIX (128 thr): for each completed iteration group, computes the 1x1-conv
//   channel mix for those 4 batches (CTAs 0..95 take one 64x64 tile each),
//   overlapping with prop's next iteration. Uses prop's idle issue slots
//   (prop issue was 15.7%) and L2-hot h.
// ---------------------------------------------------------------------------
__global__ __launch_bounds__(THREADS, 1)
void fused_kernel(const float* __restrict__ x, const float* __restrict__ A,
                  const float* __restrict__ W, const float* __restrict__ bias,
                  float* __restrict__ out) {
    __shared__ float4 part[NGRP][NT4];   // 24 KB prop partials
    __shared__ float4 xs[NT4];           // x slice,  [j*3 + lq]
    __shared__ float4 x1s[NT4];          // x1 slice, same layout

    const int t = threadIdx.x;

    if (t < NPROP) {
        // ======================= PROP threads =======================
        const int g  = t / GSZ;
        const int ti = t - g * GSZ;      // 0..191
        const int lq = ti % 3;
        const int j0 = g * JPG;

        for (int it = 0; it < NITER; ++it) {
            const int bc = blockIdx.x + it * PROP_CTAS;
            const float4* __restrict__ xp = (const float4*)(x + (size_t)bc * NT);
            const float4* __restrict__ Ap = (const float4*)(A + (size_t)bc * Nn * NT);

            if (t < NT4) xs[t] = xp[t];
            BAR_PROP();

            // ---- Pass 1: HBM stream
            float4 acc0 = make_float4(0.f, 0.f, 0.f, 0.f);
            float4 acc1 = make_float4(0.f, 0.f, 0.f, 0.f);
            {
                const float4* __restrict__ ap = Ap + (size_t)j0 * NT4;
#pragma unroll 4
                for (int jj = 0; jj < JPG; ++jj) {
                    float4 a0 = ap[jj * NT4 + ti];
                    float4 a1 = ap[jj * NT4 + ti + GSZ];
                    float4 xv = xs[(j0 + jj) * 3 + lq];
                    fma4(acc0, a0, xv);
                    fma4(acc1, a1, xv);
                }
            }
            part[g][ti]       = acc0;
            part[g][ti + GSZ] = acc1;
            BAR_PROP();

            // ---- Reduce 1
            float4 r1;
            if (t < NT4) {
                r1 = add4(add4(part[0][t], part[1][t]), add4(part[2][t], part[3][t]));
                x1s[t] = r1;
            }
            BAR_PROP();

            // ---- Pass 2: L2 re-read
            acc0 = make_float4(0.f, 0.f, 0.f, 0.f);
            acc1 = make_float4(0.f, 0.f, 0.f, 0.f);
            {
                const float4* __restrict__ ap = Ap + (size_t)j0 * NT4;
#pragma unroll 4
                for (int jj = 0; jj < JPG; ++jj) {
                    float4 a0 = __ldlu(&ap[jj * NT4 + ti]);
                    float4 a1 = __ldlu(&ap[jj * NT4 + ti + GSZ]);
                    float4 xv = x1s[(j0 + jj) * 3 + lq];
                    fma4(acc0, a0, xv);
                    fma4(acc1, a1, xv);
                }
            }
            part[g][ti]       = acc0;
            part[g][ti + GSZ] = acc1;
            BAR_PROP();

            // ---- Reduce 2 + write h rows; release to mix workers
            if (t < NT4) {
                float4 r2 = add4(add4(part[0][t], part[1][t]),
                                 add4(part[2][t], part[3][t]));
                const int b = bc / Cn;
                const int i = bc % Cn;
                ((float4*)(g_h + ((size_t)b * 2 * Cn + i) * NT))[t]      = r1;
                ((float4*)(g_h + ((size_t)b * 2 * Cn + Cn + i) * NT))[t] = r2;
                __threadfence();   // release h writes (writers only)
            }
            BAR_PROP();
            if (t == 0) atomicAdd(&g_done[it], 1u);
        }
        return;
    }

    // ======================= MIX worker threads =======================
    {
        float4* hs  = (float4*)s_pad;                 // [c][16] f4, 16 KB
        float*  Wsm = (float*)(s_pad + 16384);        // [o][c], 16 KB
        float*  bsm = (float*)(s_pad + 32768);        // 64 floats

        const int t2   = t - NPROP;                   // 0..127
        const int colq = t2 & 15;                     // f4 column
        const int oq   = t2 >> 4;                     // 0..7: outs [8oq, 8oq+8)
        const bool act = (blockIdx.x < MIX_TILES_PER_GROUP);

        if (act) {
            const float4* W4 = (const float4*)W;
#pragma unroll
            for (int k = 0; k < 8; ++k)
                ((float4*)Wsm)[t2 + NMIX * k] = W4[t2 + NMIX * k];
            if (t2 < COn) bsm[t2] = bias[t2];
        }

        for (int it = 0; it < NITER; ++it) {
            if (t2 == 0) {
                while (ld_vol_u32(&g_done[it]) < PROP_CTAS) { }
                __threadfence();   // acquire h writes
            }
            BAR_MIX();             // releases group; also orders prev compute before reload

            if (act) {
                const int b    = 4 * it + blockIdx.x / MIX_NCB;
                const int col0 = (blockIdx.x % MIX_NCB) * 64;
                const float* hb = g_h + (size_t)b * 2 * Cn * NT + col0;
#pragma unroll
                for (int k = 0; k < 8; ++k) {
                    int s = t2 + NMIX * k;            // 0..1023
                    int c = s >> 4;
                    int v = s & 15;
                    hs[s] = ((const float4*)(hb + (size_t)c * NT))[v];
                }
            }
            BAR_MIX();

            if (act) {
                const int b    = 4 * it + blockIdx.x / MIX_NCB;
                const int col0 = (blockIdx.x % MIX_NCB) * 64;

                float4 acc[8];
#pragma unroll
                for (int o = 0; o < 8; ++o) {
                    float bv = bsm[8 * oq + o];
                    acc[o] = make_float4(bv, bv, bv, bv);
                }
#pragma unroll 4
                for (int c = 0; c < 2 * Cn; ++c) {
                    float4 hv = hs[c * 16 + colq];
#pragma unroll
                    for (int o = 0; o < 8; ++o) {
                        float w = Wsm[(8 * oq + o) * 2 * Cn + c];
                        acc[o].x = fmaf(w, hv.x, acc[o].x);
                        acc[o].y = fmaf(w, hv.y, acc[o].y);
                        acc[o].z = fmaf(w, hv.z, acc[o].z);
                        acc[o].w = fmaf(w, hv.w, acc[o].w);
                    }
                }
                float* ob = out + (size_t)b * COn * NT + col0;
#pragma unroll
                for (int o = 0; o < 8; ++o)
                    ((float4*)(ob + (size_t)(8 * oq + o) * NT))[colq] = acc[o];
            }
        }
    }
}

// ---------------------------------------------------------------------------
extern "C" void kernel_launch(void* const* d_in, const int* in_sizes, int n_in,
                              void* d_out, int out_size) {
    const float* x    = (const float*)d_in[0];   // [B,C,N,T]
    const float* A    = (const float*)d_in[1];   // [B,C,N,N,T]
    const float* W    = (const float*)d_in[2];   // [C_OUT, 2C]
    const float* bias = (const float*)d_in[3];   // [C_OUT]
    float* out = (float*)d_out;                  // [B,C_OUT,N,T]

    // reset completion counters each replay (captured memset node)
    void* cp = nullptr;
    cudaGetSymbolAddress(&cp, g_done);
    cudaMemsetAsync(cp, 0, sizeof(unsigned int) * NITER);

    cudaFuncSetAttribute(fused_kernel, cudaFuncAttributeMaxDynamicSharedMemorySize,
                         PROP_PAD);

    fused_kernel<<<PROP_CTAS, THREADS, PROP_PAD>>>(x, A, W, bias, out);
}